// round 9
// baseline (speedup 1.0000x reference)
#include <cuda_runtime.h>
#include <cuda_fp16.h>
#include <cuda_fp8.h>
#include <stdint.h>

// ---------------- problem constants ----------------
#define BB 8192
#define HH 1024
#define LL 1024
#define NHEAD 5

// ---------------- GEMM config ----------------
#define TM 64
#define TN 128
#define KC 64            // K bytes per smem chunk
#define NC (HH / KC)     // 16 chunks
#define NSTAGE 4
#define NTHREADS 128     // 4 warps, 32x64 warp tiles

#define WSCALE 64.0f
#define INV_WSCALE (1.0f / 64.0f)

// smem: rowIdx (pad to 1K) then 4 stages of (A 4K | B 8K)
#define STAGE_BYTES (64 * 64 + 128 * 64)
#define SM_STAGE0 1024
#define SMEM_TOTAL (SM_STAGE0 + NSTAGE * STAGE_BYTES)

// prep kernel block ranges: block 0 = bucket; then A-convert; then W-convert
#define PREP_A_BLOCKS 1024                   // 8 warps/block -> 8192 rows
#define PREP_W_BLOCKS 1280                   // 5M elems / 16 / 256
#define PREP_BLOCKS (1 + PREP_A_BLOCKS + PREP_W_BLOCKS)

// ---------------- scratch ----------------
__device__ int g_cnt[8];
__device__ int g_rows[6 * BB];
__device__ uint8_t g_a8[(size_t)BB * HH];                // e4m3 hidden (natural order)
__device__ uint8_t g_w8[(size_t)NHEAD * LL * HH];        // e4m3 W * 64

// ---------------- PTX helpers ----------------
__device__ __forceinline__ uint32_t smem_u32(const void* p) {
    uint32_t a;
    asm("{ .reg .u64 t; cvta.to.shared.u64 t, %1; cvt.u32.u64 %0, t; }" : "=r"(a) : "l"(p));
    return a;
}
#define CP_ASYNC16(dst, src) \
    asm volatile("cp.async.cg.shared.global [%0], [%1], 16;" :: "r"(dst), "l"(src))
#define CP_COMMIT() asm volatile("cp.async.commit_group;" ::: "memory")
#define CP_WAIT2()  asm volatile("cp.async.wait_group 2;" ::: "memory")

// A fragment for m16n8k32 e4m3: lanes 0-15 rows (16B seg c16), lanes 16-31 seg c16+1.
__device__ __forceinline__ void ld_frag4a(uint32_t* f, uint32_t sbase, int rowbase,
                                          int c16, int lane) {
    int r = rowbase + (lane & 15);
    int cc = c16 + (lane >> 4);
    uint32_t addr = sbase + r * 64 + (((cc ^ ((r >> 1) & 3))) << 4);
    asm volatile("ldmatrix.sync.aligned.m8n8.x4.shared.b16 {%0,%1,%2,%3}, [%4];"
                 : "=r"(f[0]), "=r"(f[1]), "=r"(f[2]), "=r"(f[3]) : "r"(addr));
}

// B fragments for two n8 tiles at once.
__device__ __forceinline__ void ld_frag4b(uint32_t* f, uint32_t sbase, int rowbase,
                                          int c16, int lane) {
    int r = rowbase + (lane & 7) + ((lane >> 4) << 3);
    int cc = c16 + ((lane >> 3) & 1);
    uint32_t addr = sbase + r * 64 + (((cc ^ ((r >> 1) & 3))) << 4);
    asm volatile("ldmatrix.sync.aligned.m8n8.x4.shared.b16 {%0,%1,%2,%3}, [%4];"
                 : "=r"(f[0]), "=r"(f[1]), "=r"(f[2]), "=r"(f[3]) : "r"(addr));
}

__device__ __forceinline__ void mma16832(float* d, const uint32_t* a,
                                         uint32_t b0, uint32_t b1) {
    asm volatile(
        "mma.sync.aligned.m16n8k32.row.col.f32.e4m3.e4m3.f32 "
        "{%0,%1,%2,%3}, {%4,%5,%6,%7}, {%8,%9}, {%0,%1,%2,%3};"
        : "+f"(d[0]), "+f"(d[1]), "+f"(d[2]), "+f"(d[3])
        : "r"(a[0]), "r"(a[1]), "r"(a[2]), "r"(a[3]), "r"(b0), "r"(b1));
}

__device__ __forceinline__ uint8_t to_e4m3(float x) {
    return (uint8_t)__nv_cvt_float_to_fp8(x, __NV_SATFINITE, __NV_E4M3);
}
__device__ __forceinline__ uint32_t pack4_e4m3(float4 f) {
    return (uint32_t)to_e4m3(f.x) | ((uint32_t)to_e4m3(f.y) << 8) |
           ((uint32_t)to_e4m3(f.z) << 16) | ((uint32_t)to_e4m3(f.w) << 24);
}

// pack 6 group-counts into two u64 (groups 0-2 / 3-5, 21 bits each)
__device__ __forceinline__ void cnt_add(unsigned long long& c0, unsigned long long& c1,
                                        int g, unsigned long long v) {
    if (g < 3) c0 += v << (g * 21);
    else       c1 += v << ((g - 3) * 21);
}
__device__ __forceinline__ int cnt_get(unsigned long long c0, unsigned long long c1, int g) {
    unsigned long long c = (g < 3) ? c0 : c1;
    int s = ((g < 3) ? g : g - 3) * 21;
    return (int)((c >> s) & 0x1FFFFF);
}

// ---------------- fused prep ----------------
// block 0: deterministic bucket (scan, no atomics)
// blocks [1, 1+PREP_A_BLOCKS): A convert + group-5 output fill
// rest: W convert
__global__ __launch_bounds__(256)
void prep_kernel(const float* __restrict__ hs, const float* __restrict__ W,
                 const int* __restrict__ group, const int* __restrict__ labels,
                 float* __restrict__ out) {
    const int bx = blockIdx.x;
    if (bx == 0) {
        __shared__ unsigned long long s0[256], s1[256];
        const int t = threadIdx.x;
        // phase 1: per-thread counts over rows [t*32, t*32+32)
        unsigned long long c0 = 0, c1 = 0;
        int gr[32];
#pragma unroll
        for (int i = 0; i < 32; i++) {
            int g = group[t * 32 + i];
            g = (g < 0) ? 0 : ((g > 5) ? 5 : g);
            gr[i] = g;
            cnt_add(c0, c1, g, 1ull);
        }
        s0[t] = c0; s1[t] = c1;
        __syncthreads();
        // phase 2: inclusive Hillis-Steele scan
        for (int off = 1; off < 256; off <<= 1) {
            unsigned long long a0 = (t >= off) ? s0[t - off] : 0ull;
            unsigned long long a1 = (t >= off) ? s1[t - off] : 0ull;
            __syncthreads();
            s0[t] += a0; s1[t] += a1;
            __syncthreads();
        }
        unsigned long long e0 = (t > 0) ? s0[t - 1] : 0ull;
        unsigned long long e1 = (t > 0) ? s1[t - 1] : 0ull;
        if (t < 6) g_cnt[t] = cnt_get(s0[255], s1[255], t);
        // phase 3: place rows at exclusive offsets (deterministic, row order)
        int base[6];
#pragma unroll
        for (int g = 0; g < 6; g++) base[g] = cnt_get(e0, e1, g);
#pragma unroll
        for (int i = 0; i < 32; i++) {
            int g = gr[i];
            g_rows[g * BB + base[g]] = t * 32 + i;
            base[g]++;
        }
    } else if (bx <= PREP_A_BLOCKS) {
        // warp per row
        const int row = (bx - 1) * 8 + (threadIdx.x >> 5);
        const int lane = threadIdx.x & 31;
        int g = group[row];
        if (g < 0) g = 0;
        if (g > 5) g = 5;
        if (g == 5) {
            float v = (float)labels[row];
            float4 v4 = make_float4(v, v, v, v);
            float4* dp = reinterpret_cast<float4*>(out + (size_t)row * LL);
#pragma unroll
            for (int i = 0; i < 8; i++) dp[lane + i * 32] = v4;
        } else {
            const float4* src = reinterpret_cast<const float4*>(hs + (size_t)row * HH);
            uint32_t* dp = reinterpret_cast<uint32_t*>(g_a8 + (size_t)row * HH);
#pragma unroll
            for (int i = 0; i < 8; i++) dp[lane + i * 32] = pack4_e4m3(src[lane + i * 32]);
        }
    } else {
        const int i = (bx - 1 - PREP_A_BLOCKS) * 256 + threadIdx.x;   // 16-float group
        const float4* src = reinterpret_cast<const float4*>(W) + (size_t)i * 4;
        float4 f0 = src[0], f1 = src[1], f2 = src[2], f3 = src[3];
        f0.x *= WSCALE; f0.y *= WSCALE; f0.z *= WSCALE; f0.w *= WSCALE;
        f1.x *= WSCALE; f1.y *= WSCALE; f1.z *= WSCALE; f1.w *= WSCALE;
        f2.x *= WSCALE; f2.y *= WSCALE; f2.z *= WSCALE; f2.w *= WSCALE;
        f3.x *= WSCALE; f3.y *= WSCALE; f3.z *= WSCALE; f3.w *= WSCALE;
        uint4 o;
        o.x = pack4_e4m3(f0); o.y = pack4_e4m3(f1);
        o.z = pack4_e4m3(f2); o.w = pack4_e4m3(f3);
        reinterpret_cast<uint4*>(g_w8)[i] = o;
    }
}

// ---------------- FP8 MMA GEMM ----------------
// grid: (LL/TN=8, BB/TM=128, NHEAD). Early exit if row0 >= bucket count.
__global__ __launch_bounds__(NTHREADS, 3)
void gemm_fp8_kernel(const float* __restrict__ bias, float* __restrict__ out) {
    const int head = blockIdx.z;
    const int cnt = g_cnt[head];
    const int row0 = blockIdx.y * TM;
    if (row0 >= cnt) return;
    const int col0 = blockIdx.x * TN;

    extern __shared__ char smem[];
    const uint32_t sb = smem_u32(smem);
    int* rowIdx_s = reinterpret_cast<int*>(smem);

    const int tid = threadIdx.x;
    const int wid = tid >> 5;
    const int lid = tid & 31;
    const int WM = (wid & 1) * 32;       // 2 warp-rows of 32
    const int WN = (wid >> 1) * 64;      // 2 warp-cols of 64

    if (tid < TM) {
        int r = row0 + tid;
        rowIdx_s[tid] = (r < cnt) ? g_rows[head * BB + r] : -1;
    }
    __syncthreads();

    // per-thread fixed A rows for the indexed cp.async loads
    int arows[2];
#pragma unroll
    for (int l = 0; l < 2; l++) {
        int r = (l * NTHREADS + tid) >> 2;   // 0..63
        int v = rowIdx_s[r];
        arows[l] = (v < 0) ? 0 : v;          // clamp dead rows (masked at epilogue)
    }

    const uint8_t* __restrict__ bmat = g_w8 + ((size_t)head * LL + col0) * HH;

    // stage fill: A indexed-gather (2x16B) + B dense (4x16B) per thread
    auto fill_stage = [&](int s, int chunk) {
        const int k0 = chunk * KC;
        const uint32_t sbase = sb + SM_STAGE0 + s * STAGE_BYTES;
#pragma unroll
        for (int l = 0; l < 2; l++) {    // A: 64 rows x 64B
            const int q = l * NTHREADS + tid;          // 0..255
            const int r = q >> 2;
            const int seg = q & 3;
            const uint8_t* src = g_a8 + (size_t)arows[l] * HH + k0 + seg * 16;
            uint32_t dst = sbase + r * 64 + ((seg ^ ((r >> 1) & 3)) << 4);
            CP_ASYNC16(dst, src);
        }
#pragma unroll
        for (int l = 0; l < 4; l++) {    // B: 128 rows x 64B
            const int q = l * NTHREADS + tid;          // 0..511
            const int r = q >> 2;
            const int seg = q & 3;
            const uint8_t* src = bmat + (size_t)r * HH + k0 + seg * 16;
            uint32_t dst = sbase + 4096 + r * 64 + ((seg ^ ((r >> 1) & 3)) << 4);
            CP_ASYNC16(dst, src);
        }
    };

    // prologue: chunks 0..2
    fill_stage(0, 0); CP_COMMIT();
    fill_stage(1, 1); CP_COMMIT();
    fill_stage(2, 2); CP_COMMIT();

    float acc[2][8][4];
#pragma unroll
    for (int i = 0; i < 2; i++)
#pragma unroll
        for (int j = 0; j < 8; j++)
#pragma unroll
            for (int k = 0; k < 4; k++) acc[i][j][k] = 0.0f;

    for (int c = 0; c < NC; c++) {
        CP_WAIT2();                 // chunk c resident
        __syncthreads();            // + readers of reused stage drained

        // prefetch FIRST so LSU runs under the tensor pipe
        if (c + 3 < NC) fill_stage((c + 3) % NSTAGE, c + 3);
        CP_COMMIT();                // keep group count uniform

        const uint32_t sbase = sb + SM_STAGE0 + (c % NSTAGE) * STAGE_BYTES;
        const uint32_t sA = sbase;
        const uint32_t sB = sbase + 4096;

#pragma unroll
        for (int kt = 0; kt < 2; kt++) {     // two k32 halves of the 64B chunk
            const int c16 = kt * 2;
            uint32_t bfr[16];
#pragma unroll
            for (int nb = 0; nb < 4; nb++) ld_frag4b(bfr + nb * 4, sB, WN + nb * 16, c16, lid);
            uint32_t afr[8];
#pragma unroll
            for (int mt = 0; mt < 2; mt++) ld_frag4a(afr + mt * 4, sA, WM + mt * 16, c16, lid);
#pragma unroll
            for (int mt = 0; mt < 2; mt++)
#pragma unroll
                for (int nb = 0; nb < 4; nb++) {
                    mma16832(acc[mt][nb * 2 + 0], afr + mt * 4, bfr[nb * 4 + 0], bfr[nb * 4 + 1]);
                    mma16832(acc[mt][nb * 2 + 1], afr + mt * 4, bfr[nb * 4 + 2], bfr[nb * 4 + 3]);
                }
        }
    }

    // ---------------- epilogue ----------------
    const int groupID = lid >> 2;
    const int tig = lid & 3;
    const float* brow = bias + head * LL;

#pragma unroll
    for (int mt = 0; mt < 2; mt++) {
        const int mlo = WM + mt * 16 + groupID;
        const int r1 = rowIdx_s[mlo];
        const int r2 = rowIdx_s[mlo + 8];
#pragma unroll
        for (int nt = 0; nt < 8; nt++) {
            const int gc = col0 + WN + nt * 8 + tig * 2;
            const float2 bs = *reinterpret_cast<const float2*>(brow + gc);
            if (r1 >= 0) {
                float2 v = make_float2(acc[mt][nt][0] * INV_WSCALE + bs.x,
                                       acc[mt][nt][1] * INV_WSCALE + bs.y);
                *reinterpret_cast<float2*>(out + (size_t)r1 * LL + gc) = v;
            }
            if (r2 >= 0) {
                float2 v = make_float2(acc[mt][nt][2] * INV_WSCALE + bs.x,
                                       acc[mt][nt][3] * INV_WSCALE + bs.y);
                *reinterpret_cast<float2*>(out + (size_t)r2 * LL + gc) = v;
            }
        }
    }
}

// ---------------- launch ----------------
extern "C" void kernel_launch(void* const* d_in, const int* in_sizes, int n_in,
                              void* d_out, int out_size) {
    const float* hs     = (const float*)d_in[0];  // [B, H]
    const float* W      = (const float*)d_in[1];  // [5, L, H]
    const float* bias   = (const float*)d_in[2];  // [5, L]
    const int*   group  = (const int*)d_in[3];    // [B]
    const int*   labels = (const int*)d_in[4];    // [B]
    float* out = (float*)d_out;                   // [B, L]

    cudaFuncSetAttribute(gemm_fp8_kernel,
                         cudaFuncAttributeMaxDynamicSharedMemorySize, SMEM_TOTAL);

    prep_kernel<<<PREP_BLOCKS, 256>>>(hs, W, group, labels, out);

    dim3 grid(LL / TN, BB / TM, NHEAD);
    gemm_fp8_kernel<<<grid, NTHREADS, SMEM_TOTAL>>>(bias, out);
}

// round 10
// speedup vs baseline: 1.0331x; 1.0331x over previous
#include <cuda_runtime.h>
#include <cuda_fp16.h>
#include <cuda_fp8.h>
#include <stdint.h>

// ---------------- problem constants ----------------
#define BB 8192
#define HH 1024
#define LL 1024
#define NHEAD 5

// ---------------- GEMM config ----------------
#define TM 128
#define TN 128
#define KC 64            // K bytes per smem chunk
#define NC (HH / KC)     // 16 chunks
#define NSTAGE 6
#define NTHREADS 128     // 4 warps, 64x64 warp tiles

#define WSCALE 64.0f
#define INV_WSCALE (1.0f / 64.0f)

// smem: rowIdx (pad to 1K) then 6 stages of (A 8K | B 8K)
#define STAGE_BYTES (128 * 64 + 128 * 64)
#define SM_STAGE0 1024
#define SMEM_TOTAL (SM_STAGE0 + NSTAGE * STAGE_BYTES)

// prep kernel block ranges: block 0 = bucket; then A-convert; then W-convert
#define PREP_A_BLOCKS 1024                   // 8 warps/block -> 8192 rows
#define PREP_W_BLOCKS 1280                   // 5M elems / 16 / 256
#define PREP_BLOCKS (1 + PREP_A_BLOCKS + PREP_W_BLOCKS)

// ---------------- scratch ----------------
__device__ int g_cnt[8];
__device__ int g_rows[6 * BB];
__device__ uint8_t g_a8[(size_t)BB * HH];                // e4m3 hidden (natural order)
__device__ uint8_t g_w8[(size_t)NHEAD * LL * HH];        // e4m3 W * 64

// ---------------- PTX helpers ----------------
__device__ __forceinline__ uint32_t smem_u32(const void* p) {
    uint32_t a;
    asm("{ .reg .u64 t; cvta.to.shared.u64 t, %1; cvt.u32.u64 %0, t; }" : "=r"(a) : "l"(p));
    return a;
}
#define CP_ASYNC16(dst, src) \
    asm volatile("cp.async.cg.shared.global [%0], [%1], 16;" :: "r"(dst), "l"(src))
#define CP_COMMIT() asm volatile("cp.async.commit_group;" ::: "memory")
#define CP_WAIT1()  asm volatile("cp.async.wait_group 1;" ::: "memory")

// A fragment for m16n8k32 e4m3: lanes 0-15 rows (16B seg c16), lanes 16-31 seg c16+1.
__device__ __forceinline__ void ld_frag4a(uint32_t* f, uint32_t sbase, int rowbase,
                                          int c16, int lane) {
    int r = rowbase + (lane & 15);
    int cc = c16 + (lane >> 4);
    uint32_t addr = sbase + r * 64 + (((cc ^ ((r >> 1) & 3))) << 4);
    asm volatile("ldmatrix.sync.aligned.m8n8.x4.shared.b16 {%0,%1,%2,%3}, [%4];"
                 : "=r"(f[0]), "=r"(f[1]), "=r"(f[2]), "=r"(f[3]) : "r"(addr));
}

// B fragments for two n8 tiles at once.
__device__ __forceinline__ void ld_frag4b(uint32_t* f, uint32_t sbase, int rowbase,
                                          int c16, int lane) {
    int r = rowbase + (lane & 7) + ((lane >> 4) << 3);
    int cc = c16 + ((lane >> 3) & 1);
    uint32_t addr = sbase + r * 64 + (((cc ^ ((r >> 1) & 3))) << 4);
    asm volatile("ldmatrix.sync.aligned.m8n8.x4.shared.b16 {%0,%1,%2,%3}, [%4];"
                 : "=r"(f[0]), "=r"(f[1]), "=r"(f[2]), "=r"(f[3]) : "r"(addr));
}

__device__ __forceinline__ void mma16832(float* d, const uint32_t* a,
                                         uint32_t b0, uint32_t b1) {
    asm volatile(
        "mma.sync.aligned.m16n8k32.row.col.f32.e4m3.e4m3.f32 "
        "{%0,%1,%2,%3}, {%4,%5,%6,%7}, {%8,%9}, {%0,%1,%2,%3};"
        : "+f"(d[0]), "+f"(d[1]), "+f"(d[2]), "+f"(d[3])
        : "r"(a[0]), "r"(a[1]), "r"(a[2]), "r"(a[3]), "r"(b0), "r"(b1));
}

__device__ __forceinline__ uint8_t to_e4m3(float x) {
    return (uint8_t)__nv_cvt_float_to_fp8(x, __NV_SATFINITE, __NV_E4M3);
}
__device__ __forceinline__ uint32_t pack4_e4m3(float4 f) {
    return (uint32_t)to_e4m3(f.x) | ((uint32_t)to_e4m3(f.y) << 8) |
           ((uint32_t)to_e4m3(f.z) << 16) | ((uint32_t)to_e4m3(f.w) << 24);
}

// pack 6 group-counts into two u64 (groups 0-2 / 3-5, 21 bits each)
__device__ __forceinline__ void cnt_add(unsigned long long& c0, unsigned long long& c1,
                                        int g, unsigned long long v) {
    if (g < 3) c0 += v << (g * 21);
    else       c1 += v << ((g - 3) * 21);
}
__device__ __forceinline__ int cnt_get(unsigned long long c0, unsigned long long c1, int g) {
    unsigned long long c = (g < 3) ? c0 : c1;
    int s = ((g < 3) ? g : g - 3) * 21;
    return (int)((c >> s) & 0x1FFFFF);
}

// ---------------- fused prep ----------------
// block 0: deterministic bucket (scan, no atomics)
// blocks [1, 1+PREP_A_BLOCKS): A convert + group-5 output fill
// rest: W convert
__global__ __launch_bounds__(256)
void prep_kernel(const float* __restrict__ hs, const float* __restrict__ W,
                 const int* __restrict__ group, const int* __restrict__ labels,
                 float* __restrict__ out) {
    const int bx = blockIdx.x;
    if (bx == 0) {
        __shared__ unsigned long long s0[256], s1[256];
        const int t = threadIdx.x;
        unsigned long long c0 = 0, c1 = 0;
        int gr[32];
#pragma unroll
        for (int i = 0; i < 32; i++) {
            int g = group[t * 32 + i];
            g = (g < 0) ? 0 : ((g > 5) ? 5 : g);
            gr[i] = g;
            cnt_add(c0, c1, g, 1ull);
        }
        s0[t] = c0; s1[t] = c1;
        __syncthreads();
        for (int off = 1; off < 256; off <<= 1) {
            unsigned long long a0 = (t >= off) ? s0[t - off] : 0ull;
            unsigned long long a1 = (t >= off) ? s1[t - off] : 0ull;
            __syncthreads();
            s0[t] += a0; s1[t] += a1;
            __syncthreads();
        }
        unsigned long long e0 = (t > 0) ? s0[t - 1] : 0ull;
        unsigned long long e1 = (t > 0) ? s1[t - 1] : 0ull;
        if (t < 6) g_cnt[t] = cnt_get(s0[255], s1[255], t);
        int base[6];
#pragma unroll
        for (int g = 0; g < 6; g++) base[g] = cnt_get(e0, e1, g);
#pragma unroll
        for (int i = 0; i < 32; i++) {
            int g = gr[i];
            g_rows[g * BB + base[g]] = t * 32 + i;
            base[g]++;
        }
    } else if (bx <= PREP_A_BLOCKS) {
        const int row = (bx - 1) * 8 + (threadIdx.x >> 5);
        const int lane = threadIdx.x & 31;
        int g = group[row];
        if (g < 0) g = 0;
        if (g > 5) g = 5;
        if (g == 5) {
            float v = (float)labels[row];
            float4 v4 = make_float4(v, v, v, v);
            float4* dp = reinterpret_cast<float4*>(out + (size_t)row * LL);
#pragma unroll
            for (int i = 0; i < 8; i++) dp[lane + i * 32] = v4;
        } else {
            const float4* src = reinterpret_cast<const float4*>(hs + (size_t)row * HH);
            uint32_t* dp = reinterpret_cast<uint32_t*>(g_a8 + (size_t)row * HH);
#pragma unroll
            for (int i = 0; i < 8; i++) dp[lane + i * 32] = pack4_e4m3(src[lane + i * 32]);
        }
    } else {
        const int i = (bx - 1 - PREP_A_BLOCKS) * 256 + threadIdx.x;   // 16-float group
        const float4* src = reinterpret_cast<const float4*>(W) + (size_t)i * 4;
        float4 f0 = src[0], f1 = src[1], f2 = src[2], f3 = src[3];
        f0.x *= WSCALE; f0.y *= WSCALE; f0.z *= WSCALE; f0.w *= WSCALE;
        f1.x *= WSCALE; f1.y *= WSCALE; f1.z *= WSCALE; f1.w *= WSCALE;
        f2.x *= WSCALE; f2.y *= WSCALE; f2.z *= WSCALE; f2.w *= WSCALE;
        f3.x *= WSCALE; f3.y *= WSCALE; f3.z *= WSCALE; f3.w *= WSCALE;
        uint4 o;
        o.x = pack4_e4m3(f0); o.y = pack4_e4m3(f1);
        o.z = pack4_e4m3(f2); o.w = pack4_e4m3(f3);
        reinterpret_cast<uint4*>(g_w8)[i] = o;
    }
}

// ---------------- FP8 MMA GEMM ----------------
// grid: (LL/TN=8, BB/TM=64, NHEAD). Early exit if row0 >= bucket count.
// 2 chunks per sync iteration, 6 stages.
__global__ __launch_bounds__(NTHREADS)
void gemm_fp8_kernel(const float* __restrict__ bias, float* __restrict__ out) {
    const int head = blockIdx.z;
    const int cnt = g_cnt[head];
    const int row0 = blockIdx.y * TM;
    if (row0 >= cnt) return;
    const int col0 = blockIdx.x * TN;

    extern __shared__ char smem[];
    const uint32_t sb = smem_u32(smem);
    int* rowIdx_s = reinterpret_cast<int*>(smem);

    const int tid = threadIdx.x;
    const int wid = tid >> 5;
    const int lid = tid & 31;
    const int WM = (wid & 1) * 64;       // 2 warp-rows of 64
    const int WN = (wid >> 1) * 64;      // 2 warp-cols of 64

    if (tid < TM) {
        int r = row0 + tid;
        rowIdx_s[tid] = (r < cnt) ? g_rows[head * BB + r] : -1;
    }
    __syncthreads();

    // per-thread fixed A rows for the indexed cp.async loads
    int arows[4];
#pragma unroll
    for (int l = 0; l < 4; l++) {
        int r = (l * NTHREADS + tid) >> 2;
        int v = rowIdx_s[r];
        arows[l] = (v < 0) ? 0 : v;      // clamp dead rows (masked at epilogue)
    }

    const uint8_t* __restrict__ bmat = g_w8 + ((size_t)head * LL + col0) * HH;

    // stage fill: A indexed-gather + B dense, 8 x 16B cp.async per thread
    auto fill_stage = [&](int s, int chunk) {
        const int k0 = chunk * KC;
        const uint32_t sbase = sb + SM_STAGE0 + s * STAGE_BYTES;
#pragma unroll
        for (int l = 0; l < 4; l++) {    // A: 128 rows x 64B
            const int q = l * NTHREADS + tid;          // 0..511
            const int r = q >> 2;
            const int seg = q & 3;
            const uint8_t* src = g_a8 + (size_t)arows[l] * HH + k0 + seg * 16;
            uint32_t dst = sbase + r * 64 + ((seg ^ ((r >> 1) & 3)) << 4);
            CP_ASYNC16(dst, src);
        }
#pragma unroll
        for (int l = 0; l < 4; l++) {    // B: 128 rows x 64B
            const int q = l * NTHREADS + tid;
            const int r = q >> 2;
            const int seg = q & 3;
            const uint8_t* src = bmat + (size_t)r * HH + k0 + seg * 16;
            uint32_t dst = sbase + 8192 + r * 64 + ((seg ^ ((r >> 1) & 3)) << 4);
            CP_ASYNC16(dst, src);
        }
    };

    // prologue: chunks 0..3 in two committed pairs
    fill_stage(0, 0); fill_stage(1, 1); CP_COMMIT();
    fill_stage(2, 2); fill_stage(3, 3); CP_COMMIT();

    float acc[4][8][4];
#pragma unroll
    for (int i = 0; i < 4; i++)
#pragma unroll
        for (int j = 0; j < 8; j++)
#pragma unroll
            for (int k = 0; k < 4; k++) acc[i][j][k] = 0.0f;

    for (int p = 0; p < NC / 2; p++) {           // pair index: chunks 2p, 2p+1
        CP_WAIT1();                 // pair p resident (1 newer group may be in flight)
        __syncthreads();            // readers of reused stages drained

        // prefetch next pair FIRST so LSU runs under the tensor pipe
        const int nchunk = 2 * p + 4;
        if (nchunk < NC) {
            fill_stage(nchunk % NSTAGE, nchunk);
            fill_stage((nchunk + 1) % NSTAGE, nchunk + 1);
        }
        CP_COMMIT();                // keep group count uniform

#pragma unroll
        for (int half = 0; half < 2; half++) {
            const int chunk = 2 * p + half;
            const uint32_t sbase = sb + SM_STAGE0 + (chunk % NSTAGE) * STAGE_BYTES;
            const uint32_t sA = sbase;
            const uint32_t sB = sbase + 8192;
#pragma unroll
            for (int kt = 0; kt < 2; kt++) {     // two k32 halves of the 64B chunk
                const int c16 = kt * 2;
                uint32_t bfr[16];
#pragma unroll
                for (int nb = 0; nb < 4; nb++)
                    ld_frag4b(bfr + nb * 4, sB, WN + nb * 16, c16, lid);
                uint32_t afr[16];
#pragma unroll
                for (int mt = 0; mt < 4; mt++)
                    ld_frag4a(afr + mt * 4, sA, WM + mt * 16, c16, lid);
#pragma unroll
                for (int mt = 0; mt < 4; mt++)
#pragma unroll
                    for (int nb = 0; nb < 4; nb++) {
                        mma16832(acc[mt][nb * 2 + 0], afr + mt * 4,
                                 bfr[nb * 4 + 0], bfr[nb * 4 + 1]);
                        mma16832(acc[mt][nb * 2 + 1], afr + mt * 4,
                                 bfr[nb * 4 + 2], bfr[nb * 4 + 3]);
                    }
            }
        }
    }

    // ---------------- epilogue ----------------
    const int groupID = lid >> 2;
    const int tig = lid & 3;
    const float* brow = bias + head * LL;

#pragma unroll
    for (int mt = 0; mt < 4; mt++) {
        const int mlo = WM + mt * 16 + groupID;
        const int r1 = rowIdx_s[mlo];
        const int r2 = rowIdx_s[mlo + 8];
#pragma unroll
        for (int nt = 0; nt < 8; nt++) {
            const int gc = col0 + WN + nt * 8 + tig * 2;
            const float2 bs = *reinterpret_cast<const float2*>(brow + gc);
            if (r1 >= 0) {
                float2 v = make_float2(acc[mt][nt][0] * INV_WSCALE + bs.x,
                                       acc[mt][nt][1] * INV_WSCALE + bs.y);
                *reinterpret_cast<float2*>(out + (size_t)r1 * LL + gc) = v;
            }
            if (r2 >= 0) {
                float2 v = make_float2(acc[mt][nt][2] * INV_WSCALE + bs.x,
                                       acc[mt][nt][3] * INV_WSCALE + bs.y);
                *reinterpret_cast<float2*>(out + (size_t)r2 * LL + gc) = v;
            }
        }
    }
}

// ---------------- launch ----------------
extern "C" void kernel_launch(void* const* d_in, const int* in_sizes, int n_in,
                              void* d_out, int out_size) {
    const float* hs     = (const float*)d_in[0];  // [B, H]
    const float* W      = (const float*)d_in[1];  // [5, L, H]
    const float* bias   = (const float*)d_in[2];  // [5, L]
    const int*   group  = (const int*)d_in[3];    // [B]
    const int*   labels = (const int*)d_in[4];    // [B]
    float* out = (float*)d_out;                   // [B, L]

    cudaFuncSetAttribute(gemm_fp8_kernel,
                         cudaFuncAttributeMaxDynamicSharedMemorySize, SMEM_TOTAL);

    prep_kernel<<<PREP_BLOCKS, 256>>>(hs, W, group, labels, out);

    dim3 grid(LL / TN, BB / TM, NHEAD);
    gemm_fp8_kernel<<<grid, NTHREADS, SMEM_TOTAL>>>(bias, out);
}